// round 1
// baseline (speedup 1.0000x reference)
#include <cuda_runtime.h>
#include <math.h>
#include <stdint.h>

#define BB 128
#define RR 4096
#define DD 256
#define NROW (BB * RR)

// Static device scratch (no allocations allowed)
__device__ float g_dot[NROW];
__device__ float g_ss[NROW];
__device__ float g_coef[NROW];
__device__ int   g_cnt[BB];
__device__ int   g_qidx[BB];

// ---------------------------------------------------------------------------
// Kernel 0: decode query_rels. May be int64 or int32 depending on jax x64
// config. Detect: if data is int64 little-endian with values < 4096, the
// high 32-bit word of every element is 0. Check the first 64 pairs (512 B,
// safe under BOTH interpretations).
// ---------------------------------------------------------------------------
__global__ void decode_qidx_kernel(const void* __restrict__ qr) {
    __shared__ int odd_nonzero;
    int t = threadIdx.x;  // 128 threads
    if (t == 0) odd_nonzero = 0;
    __syncthreads();
    const int* p32 = (const int*)qr;
    if (t < 64) {
        if (p32[2 * t + 1] != 0) atomicOr(&odd_nonzero, 1);
    }
    __syncthreads();
    bool is64 = (odd_nonzero == 0);
    if (t < BB) {
        int v;
        if (is64) {
            v = (int)((const long long*)qr)[t];
        } else {
            v = p32[t];
        }
        g_qidx[t] = v;
    }
}

// ---------------------------------------------------------------------------
// Kernel 1: fused copy + per-row dot(r_i, q_b) + per-row sum-of-squares.
// One warp per row (256 floats). Lane l handles float4 slots l and l+32.
// ---------------------------------------------------------------------------
__global__ void __launch_bounds__(256) fuse_copy_sims_kernel(
    const float* __restrict__ in, float* __restrict__ out) {
    int warp = (int)((blockIdx.x * blockDim.x + threadIdx.x) >> 5);
    int lane = threadIdx.x & 31;
    if (warp >= NROW) return;
    int b = warp >> 12;  // / RR
    int qidx = g_qidx[b];

    const float4* rp = (const float4*)(in + (size_t)warp * DD);
    const float4* qp = (const float4*)(in + ((size_t)b * RR + qidx) * DD);
    float4* op = (float4*)(out + (size_t)warp * DD);

    float4 a0 = rp[lane];
    float4 a1 = rp[lane + 32];
    float4 q0 = qp[lane];
    float4 q1 = qp[lane + 32];

    op[lane]      = a0;
    op[lane + 32] = a1;

    float dot = a0.x * q0.x + a0.y * q0.y + a0.z * q0.z + a0.w * q0.w
              + a1.x * q1.x + a1.y * q1.y + a1.z * q1.z + a1.w * q1.w;
    float ss  = a0.x * a0.x + a0.y * a0.y + a0.z * a0.z + a0.w * a0.w
              + a1.x * a1.x + a1.y * a1.y + a1.z * a1.z + a1.w * a1.w;

#pragma unroll
    for (int o = 16; o > 0; o >>= 1) {
        dot += __shfl_xor_sync(0xFFFFFFFFu, dot, o);
        ss  += __shfl_xor_sync(0xFFFFFFFFu, ss, o);
    }
    if (lane == 0) {
        g_dot[warp] = dot;
        g_ss[warp]  = ss;
    }
}

// ---------------------------------------------------------------------------
// Block reductions (256 threads)
// ---------------------------------------------------------------------------
__device__ __forceinline__ float block_reduce_max(float v, float* red) {
    int t = threadIdx.x;
    red[t] = v;
    __syncthreads();
#pragma unroll
    for (int s = 128; s > 0; s >>= 1) {
        if (t < s) red[t] = fmaxf(red[t], red[t + s]);
        __syncthreads();
    }
    float r = red[0];
    __syncthreads();
    return r;
}

__device__ __forceinline__ float block_reduce_sum(float v, float* red) {
    int t = threadIdx.x;
    red[t] = v;
    __syncthreads();
#pragma unroll
    for (int s = 128; s > 0; s >>= 1) {
        if (t < s) red[t] += red[t + s];
        __syncthreads();
    }
    float r = red[0];
    __syncthreads();
    return r;
}

// ---------------------------------------------------------------------------
// Kernel 2: per-batch gating + masked softmax + coefficient computation.
// 128 CTAs x 256 threads; thread t handles i = t + k*256, k in [0,16).
// Writes g_coef (strength*adjusted, 0 when unmasked) and g_cnt (mask count).
// ---------------------------------------------------------------------------
__global__ void __launch_bounds__(256) weights_kernel(
    const float* __restrict__ thr_raw, const float* __restrict__ str_raw,
    const float* __restrict__ wscale,  const float* __restrict__ temp_p) {
    __shared__ float red[256];
    int b = blockIdx.x;
    int t = threadIdx.x;

    float thr = 1.0f / (1.0f + expf(-thr_raw[0]));
    float strength = 0.2f / (1.0f + expf(-str_raw[0]));
    float ws = wscale[0];
    float temp = fminf(fmaxf(temp_p[0], 0.1f), 10.0f);

    int qidx = g_qidx[b];
    float qn = fmaxf(sqrtf(g_ss[(size_t)b * RR + qidx]), 1e-12f);

    float sims[16];
    bool  msk[16];
    float lmax = -1e9f;
    int   lcnt = 0;
#pragma unroll
    for (int k = 0; k < 16; k++) {
        int i = t + k * 256;
        size_t idx = (size_t)b * RR + i;
        float nrm = fmaxf(sqrtf(g_ss[idx]), 1e-12f);
        float s = g_dot[idx] / (nrm * qn);
        if (i == qidx) s = -1.0f;
        sims[k] = s;
        float sw = 1.0f / (1.0f + expf(-(s - thr) * 10.0f));
        bool m = sw > 0.5f;
        msk[k] = m;
        if (m) {
            lmax = fmaxf(lmax, s / temp);
            lcnt++;
        }
    }

    int total = (int)block_reduce_sum((float)lcnt, red);
    if (total == 0) {
        if (t == 0) g_cnt[b] = 0;
        return;
    }

    float m = block_reduce_max(lmax, red);

    float lz = 0.0f;
#pragma unroll
    for (int k = 0; k < 16; k++) {
        if (msk[k]) lz += expf(sims[k] / temp - m);
        // unmasked entries: exp(-1e9 - m) underflows to exactly 0 in fp32
    }
    float Z = block_reduce_sum(lz, red);

    float c[16];
    float lS = 0.0f;
#pragma unroll
    for (int k = 0; k < 16; k++) {
        if (msk[k]) {
            float s = sims[k];
            float sw = 1.0f / (1.0f + expf(-(s - thr) * 10.0f));
            float w = expf(s / temp - m) / Z;
            c[k] = w * sw * (1.0f + ws * s);
            lS += c[k];
        } else {
            c[k] = 0.0f;
        }
    }
    float S = block_reduce_sum(lS, red);
    float inv = strength / (S + 1e-8f);

#pragma unroll
    for (int k = 0; k < 16; k++) {
        int i = t + k * 256;
        g_coef[(size_t)b * RR + i] = c[k] * inv;
    }
    if (t == 0) g_cnt[b] = total;
}

// ---------------------------------------------------------------------------
// Kernel 3: write the updated query row. Early-exit when no valid neighbor
// (row already correct from the copy). Otherwise sparse weighted sum over
// rows with nonzero coefficient.
// ---------------------------------------------------------------------------
__global__ void __launch_bounds__(256) apply_kernel(
    const float* __restrict__ in, float* __restrict__ out,
    const float* __restrict__ str_raw) {
    int b = blockIdx.x;
    if (g_cnt[b] == 0) return;
    int t = threadIdx.x;  // dim index
    __shared__ float sc[256];

    float acc = 0.0f;
    for (int c0 = 0; c0 < RR; c0 += 256) {
        __syncthreads();
        sc[t] = g_coef[(size_t)b * RR + c0 + t];
        __syncthreads();
#pragma unroll 4
        for (int j = 0; j < 256; j++) {
            float cf = sc[j];
            if (cf != 0.0f) {
                acc += cf * in[((size_t)b * RR + c0 + j) * DD + t];
            }
        }
    }

    float strength = 0.2f / (1.0f + expf(-str_raw[0]));
    int qidx = g_qidx[b];
    float q = in[((size_t)b * RR + qidx) * DD + t];
    out[((size_t)b * RR + qidx) * DD + t] = (1.0f - strength) * q + acc;
}

// ---------------------------------------------------------------------------
extern "C" void kernel_launch(void* const* d_in, const int* in_sizes, int n_in,
                              void* d_out, int out_size) {
    const float* reps    = (const float*)d_in[0];
    const void*  qrels   = d_in[1];
    const float* thr_raw = (const float*)d_in[2];
    const float* str_raw = (const float*)d_in[3];
    const float* wscale  = (const float*)d_in[4];
    const float* temp_p  = (const float*)d_in[5];
    float* out = (float*)d_out;

    decode_qidx_kernel<<<1, 128>>>(qrels);

    // one warp per row: NROW warps, 8 warps per 256-thread CTA
    fuse_copy_sims_kernel<<<NROW / 8, 256>>>(reps, out);

    weights_kernel<<<BB, 256>>>(thr_raw, str_raw, wscale, temp_p);

    apply_kernel<<<BB, 256>>>(reps, out, str_raw);
}

// round 2
// speedup vs baseline: 1.0604x; 1.0604x over previous
#include <cuda_runtime.h>
#include <math.h>
#include <stdint.h>

#define BB 128
#define RR 4096
#define DD 256
#define NROW (BB * RR)

// Static device scratch (no allocations allowed)
__device__ float g_dot[NROW];
__device__ float g_ss[NROW];
__device__ int   g_qidx[BB];

// ---------------------------------------------------------------------------
// Kernel 0: decode query_rels (int64 vs int32 autodetect).
// If int64 LE with values < 4096, every high word is 0. Checking the first
// 64 pairs (512 B) is safe under both interpretations.
// ---------------------------------------------------------------------------
__global__ void decode_qidx_kernel(const void* __restrict__ qr) {
    __shared__ int odd_nonzero;
    int t = threadIdx.x;  // 128 threads
    if (t == 0) odd_nonzero = 0;
    __syncthreads();
    const int* p32 = (const int*)qr;
    if (t < 64) {
        if (p32[2 * t + 1] != 0) atomicOr(&odd_nonzero, 1);
    }
    __syncthreads();
    bool is64 = (odd_nonzero == 0);
    if (t < BB) {
        g_qidx[t] = is64 ? (int)((const long long*)qr)[t] : p32[t];
    }
}

// ---------------------------------------------------------------------------
// Kernel 1: fused copy + per-row dot(r_i, q_b) + per-row sum-of-squares.
// One warp per row. Each CTA (8 rows) is entirely within one batch
// (4096 rows / 8 = 512 CTAs per batch), so q is staged ONCE per CTA in
// shared memory — removes ~450 MB of L2 read traffic vs per-warp q loads.
// Streaming loads/stores (__ldcs/__stcs) keep the 1 GB stream out of L2.
// ---------------------------------------------------------------------------
__global__ void __launch_bounds__(256) fuse_copy_sims_kernel(
    const float* __restrict__ in, float* __restrict__ out) {
    __shared__ float qs[DD];
    int cta = blockIdx.x;
    int b = cta >> 9;            // 512 CTAs per batch
    int qidx = g_qidx[b];

    // cooperative q stage: 256 threads, 256 floats
    qs[threadIdx.x] = __ldg(in + ((size_t)b * RR + qidx) * DD + threadIdx.x);
    __syncthreads();

    int warp = threadIdx.x >> 5;
    int lane = threadIdx.x & 31;
    int row = cta * 8 + warp;

    const float4* rp = (const float4*)(in + (size_t)row * DD);
    float4* op = (float4*)(out + (size_t)row * DD);

    float4 a0 = __ldcs(rp + lane);
    float4 a1 = __ldcs(rp + lane + 32);
    __stcs(op + lane, a0);
    __stcs(op + lane + 32, a1);

    float4 q0 = *(const float4*)(qs + 4 * lane);
    float4 q1 = *(const float4*)(qs + 128 + 4 * lane);

    float dot = a0.x * q0.x + a0.y * q0.y + a0.z * q0.z + a0.w * q0.w
              + a1.x * q1.x + a1.y * q1.y + a1.z * q1.z + a1.w * q1.w;
    float ss  = a0.x * a0.x + a0.y * a0.y + a0.z * a0.z + a0.w * a0.w
              + a1.x * a1.x + a1.y * a1.y + a1.z * a1.z + a1.w * a1.w;

#pragma unroll
    for (int o = 16; o > 0; o >>= 1) {
        dot += __shfl_xor_sync(0xFFFFFFFFu, dot, o);
        ss  += __shfl_xor_sync(0xFFFFFFFFu, ss, o);
    }
    if (lane == 0) {
        g_dot[row] = dot;
        g_ss[row]  = ss;
    }
}

// ---------------------------------------------------------------------------
// Block reductions (256 threads)
// ---------------------------------------------------------------------------
__device__ __forceinline__ float block_reduce_max(float v, float* red) {
    int t = threadIdx.x;
    red[t] = v;
    __syncthreads();
#pragma unroll
    for (int s = 128; s > 0; s >>= 1) {
        if (t < s) red[t] = fmaxf(red[t], red[t + s]);
        __syncthreads();
    }
    float r = red[0];
    __syncthreads();
    return r;
}

__device__ __forceinline__ float block_reduce_sum(float v, float* red) {
    int t = threadIdx.x;
    red[t] = v;
    __syncthreads();
#pragma unroll
    for (int s = 128; s > 0; s >>= 1) {
        if (t < s) red[t] += red[t + s];
        __syncthreads();
    }
    float r = red[0];
    __syncthreads();
    return r;
}

// ---------------------------------------------------------------------------
// Kernel 2: per-batch gating + masked softmax + coefficient computation +
// sparse weighted apply, fused. 128 CTAs x 256 threads; thread t handles
// rows i = t + k*256. Nonzero coefficients are compacted into a shared
// list; the apply phase is O(nnz) row loads (typically nnz == 0 -> pure
// early exit; copy already wrote the correct row).
// ---------------------------------------------------------------------------
__global__ void __launch_bounds__(256) weights_apply_kernel(
    const float* __restrict__ in, float* __restrict__ out,
    const float* __restrict__ thr_raw, const float* __restrict__ str_raw,
    const float* __restrict__ wscale,  const float* __restrict__ temp_p) {
    __shared__ float red[256];
    __shared__ int   s_idx[RR];
    __shared__ float s_cf[RR];
    __shared__ int   s_n;
    int b = blockIdx.x;
    int t = threadIdx.x;

    float thr = 1.0f / (1.0f + expf(-thr_raw[0]));
    float strength = 0.2f / (1.0f + expf(-str_raw[0]));
    float ws = wscale[0];
    float temp = fminf(fmaxf(temp_p[0], 0.1f), 10.0f);

    if (t == 0) s_n = 0;

    int qidx = g_qidx[b];
    float qn = fmaxf(sqrtf(g_ss[(size_t)b * RR + qidx]), 1e-12f);

    float sims[16];
    bool  msk[16];
    float lmax = -1e9f;
    int   lcnt = 0;
#pragma unroll
    for (int k = 0; k < 16; k++) {
        int i = t + k * 256;
        size_t idx = (size_t)b * RR + i;
        float nrm = fmaxf(sqrtf(g_ss[idx]), 1e-12f);
        float s = g_dot[idx] / (nrm * qn);
        if (i == qidx) s = -1.0f;
        sims[k] = s;
        float sw = 1.0f / (1.0f + expf(-(s - thr) * 10.0f));
        bool m = sw > 0.5f;
        msk[k] = m;
        if (m) {
            lmax = fmaxf(lmax, s / temp);
            lcnt++;
        }
    }

    int total = (int)block_reduce_sum((float)lcnt, red);
    if (total == 0) return;  // copy already wrote the unchanged q row

    float m = block_reduce_max(lmax, red);

    float lz = 0.0f;
#pragma unroll
    for (int k = 0; k < 16; k++) {
        if (msk[k]) lz += expf(sims[k] / temp - m);
        // unmasked entries: exp(-1e9) underflows to exactly 0 in fp32
    }
    float Z = block_reduce_sum(lz, red);

    float c[16];
    float lS = 0.0f;
#pragma unroll
    for (int k = 0; k < 16; k++) {
        if (msk[k]) {
            float s = sims[k];
            float sw = 1.0f / (1.0f + expf(-(s - thr) * 10.0f));
            float w = expf(s / temp - m) / Z;
            c[k] = w * sw * (1.0f + ws * s);
            lS += c[k];
        } else {
            c[k] = 0.0f;
        }
    }
    float S = block_reduce_sum(lS, red);
    float inv = strength / (S + 1e-8f);

    // compact nonzero (idx, coef) pairs into shared
#pragma unroll
    for (int k = 0; k < 16; k++) {
        if (msk[k]) {
            int slot = atomicAdd(&s_n, 1);
            s_idx[slot] = t + k * 256;
            s_cf[slot]  = c[k] * inv;
        }
    }
    __syncthreads();

    // sparse weighted sum over nnz rows; thread t = dim index
    int nnz = s_n;
    float acc = 0.0f;
    for (int j = 0; j < nnz; j++) {
        int i = s_idx[j];
        acc += s_cf[j] * in[((size_t)b * RR + i) * DD + t];
    }

    float q = in[((size_t)b * RR + qidx) * DD + t];
    out[((size_t)b * RR + qidx) * DD + t] = (1.0f - strength) * q + acc;
}

// ---------------------------------------------------------------------------
extern "C" void kernel_launch(void* const* d_in, const int* in_sizes, int n_in,
                              void* d_out, int out_size) {
    const float* reps    = (const float*)d_in[0];
    const void*  qrels   = d_in[1];
    const float* thr_raw = (const float*)d_in[2];
    const float* str_raw = (const float*)d_in[3];
    const float* wscale  = (const float*)d_in[4];
    const float* temp_p  = (const float*)d_in[5];
    float* out = (float*)d_out;

    decode_qidx_kernel<<<1, 128>>>(qrels);

    // one warp per row: 8 rows per 256-thread CTA
    fuse_copy_sims_kernel<<<NROW / 8, 256>>>(reps, out);

    weights_apply_kernel<<<BB, 256>>>(reps, out, thr_raw, str_raw, wscale, temp_p);
}